// round 2
// baseline (speedup 1.0000x reference)
#include <cuda_runtime.h>

// PINN 5-jet propagation, 2 points/thread via packed f32x2 (FFMA2) math.
// Per point: push (val, d1..d4) through 1->8 tanh -> 8 tanh -> 2 linear.
// Outputs per point: [u, u_x, u_xx, w, w_x, w_xx, w_xxx, w_xxxx].

using u64 = unsigned long long;

#define PKC(h) ((((u64)(h)) << 32) | (u64)(h))

__device__ __forceinline__ u64 pk(float a, float b) {
    u64 r; asm("mov.b64 %0, {%1, %2};" : "=l"(r) : "f"(a), "f"(b)); return r;
}
__device__ __forceinline__ void upk(u64 v, float& a, float& b) {
    asm("mov.b64 {%0, %1}, %2;" : "=f"(a), "=f"(b) : "l"(v));
}
__device__ __forceinline__ u64 fma2(u64 a, u64 b, u64 c) {
    u64 r; asm("fma.rn.f32x2 %0, %1, %2, %3;" : "=l"(r) : "l"(a), "l"(b), "l"(c)); return r;
}
__device__ __forceinline__ u64 mul2(u64 a, u64 b) {
    u64 r; asm("mul.rn.f32x2 %0, %1, %2;" : "=l"(r) : "l"(a), "l"(b)); return r;
}

// tanh via exp: t = 1 - 2/(exp(2z)+1); s = 1 - t^2. MUFU-accurate (~1e-6).
__device__ __forceinline__ float tanh_fast(float z, float& s) {
    float e, r;
    asm("ex2.approx.f32 %0, %1;" : "=f"(e) : "f"(z * 2.8853900817779268f)); // 2*log2(e)
    asm("rcp.approx.f32 %0, %1;" : "=f"(r) : "f"(e + 1.0f));
    float t = fmaf(-2.0f, r, 1.0f);
    s = fmaf(-t, t, 1.0f);
    return t;
}
__device__ __forceinline__ void tanh2(u64 z, u64& t, u64& s) {
    float z0, z1; upk(z, z0, z1);
    float s0, s1;
    float t0 = tanh_fast(z0, s0);
    float t1 = tanh_fast(z1, s1);
    t = pk(t0, t1);
    s = pk(s0, s1);
}

__global__ __launch_bounds__(256)
void pinn_jet2_kernel(const float* __restrict__ x,
                      const float* __restrict__ gW0, const float* __restrict__ gb0,
                      const float* __restrict__ gW1, const float* __restrict__ gb1,
                      const float* __restrict__ gW2, const float* __restrict__ gb2,
                      float* __restrict__ out, int n)
{
    // Duplicated (broadcast-packed) weights in shared, incl. precomputed W0 powers.
    __shared__ u64 sW0[8], sW0p2[8], sW0p3[8], sW0p4[8], sb0[8];
    __shared__ u64 sW1[64], sb1[8], sW2u[8], sW2v[8], sb2[2];
    {
        int t = threadIdx.x;
        if (t < 64) { float w = gW1[t]; sW1[t] = pk(w, w); }
        if (t < 8) {
            float w = gW0[t], w2 = w * w;
            sW0[t]   = pk(w, w);
            sW0p2[t] = pk(w2, w2);
            sW0p3[t] = pk(w2 * w, w2 * w);
            sW0p4[t] = pk(w2 * w2, w2 * w2);
            float bb = gb0[t]; sb0[t] = pk(bb, bb);
            float b1v = gb1[t]; sb1[t] = pk(b1v, b1v);
            float wu = gW2[t];     sW2u[t] = pk(wu, wu);
            float wv = gW2[8 + t]; sW2v[t] = pk(wv, wv);
        }
        if (t < 2) { float bb = gb2[t]; sb2[t] = pk(bb, bb); }
    }
    __syncthreads();

    const u64 Z    = 0ULL;
    const u64 C3   = PKC(0x40400000u);  //  3
    const u64 C4   = PKC(0x40800000u);  //  4
    const u64 C6   = PKC(0x40c00000u);  //  6
    const u64 CN2  = PKC(0xc0000000u);  // -2
    const u64 C16  = PKC(0x41800000u);  // 16
    const u64 CN24 = PKC(0xc1c00000u);  // -24

    int gid = blockIdx.x * blockDim.x + threadIdx.x;
    int i0 = gid * 2;
    if (i0 >= n) return;

    float x0, x1;
    if (i0 + 1 < n) {
        float2 xx = reinterpret_cast<const float2*>(x)[gid];
        x0 = xx.x; x1 = xx.y;
    } else {
        x0 = x[i0]; x1 = x0;
    }
    const u64 xv = pk(x0, x1);

    // ---- Layer 0: scalar input -> tanh jet (z1=w, z2..z4=0) ----
    u64 h0[8], h1[8], h2[8], h3[8], h4[8];
#pragma unroll
    for (int j = 0; j < 8; ++j) {
        u64 z = fma2(sW0[j], xv, sb0[j]);
        u64 t, s; tanh2(z, t, s);
        u64 ts = mul2(t, s);
        u64 tt = mul2(t, t);
        u64 d2 = mul2(ts, CN2);
        u64 d3 = mul2(s, fma2(C6, tt, CN2));
        u64 d4 = mul2(ts, fma2(CN24, tt, C16));
        h0[j] = t;
        h1[j] = mul2(s,  sW0[j]);
        h2[j] = mul2(d2, sW0p2[j]);
        h3[j] = mul2(d3, sW0p3[j]);
        h4[j] = mul2(d4, sW0p4[j]);
    }

    // ---- Layer 1 (8x8) + tanh jet, output layer fused ----
    u64 U0 = sb2[0], U1 = Z, U2 = Z;
    u64 V0 = sb2[1], V1 = Z, V2 = Z, V3 = Z, V4 = Z;

#pragma unroll
    for (int j = 0; j < 8; ++j) {
        u64 z0 = sb1[j], z1 = Z, z2 = Z, z3 = Z, z4 = Z;
#pragma unroll
        for (int k = 0; k < 8; ++k) {
            u64 w = sW1[j * 8 + k];
            z0 = fma2(w, h0[k], z0);
            z1 = fma2(w, h1[k], z1);
            z2 = fma2(w, h2[k], z2);
            z3 = fma2(w, h3[k], z3);
            z4 = fma2(w, h4[k], z4);
        }
        u64 t, s; tanh2(z0, t, s);
        u64 ts = mul2(t, s);
        u64 tt = mul2(t, t);
        u64 d2 = mul2(ts, CN2);
        u64 d3 = mul2(s, fma2(C6, tt, CN2));
        u64 d4 = mul2(ts, fma2(CN24, tt, C16));

        u64 z1_2 = mul2(z1, z1);
        // Faa di Bruno orders 0..4
        u64 g0 = t;
        u64 g1 = mul2(s, z1);
        u64 g2 = fma2(d2, z1_2, mul2(s, z2));
        u64 g3 = mul2(s, z3);
        g3 = fma2(mul2(d3, z1_2), z1, g3);
        g3 = fma2(mul2(d2, C3), mul2(z1, z2), g3);
        u64 g4 = mul2(s, z4);
        {
            u64 a = mul2(z2, z2);           // z2^2
            u64 b = mul2(z1, z3);           // z1*z3
            u64 inner = mul2(C4, b);
            inner = fma2(C3, a, inner);     // 3 z2^2 + 4 z1 z3
            g4 = fma2(d2, inner, g4);
            g4 = fma2(mul2(C6, d3), mul2(z1_2, z2), g4);
            g4 = fma2(d4, mul2(z1_2, z1_2), g4);
        }

        u64 wu = sW2u[j], wv = sW2v[j];
        U0 = fma2(wu, g0, U0);
        U1 = fma2(wu, g1, U1);
        U2 = fma2(wu, g2, U2);
        V0 = fma2(wv, g0, V0);
        V1 = fma2(wv, g1, V1);
        V2 = fma2(wv, g2, V2);
        V3 = fma2(wv, g3, V3);
        V4 = fma2(wv, g4, V4);
    }

    // ---- Store 2 points x 8 outputs ----
    float au0, bu0, au1, bu1, au2, bu2;
    float av0, bv0, av1, bv1, av2, bv2, av3, bv3, av4, bv4;
    upk(U0, au0, bu0); upk(U1, au1, bu1); upk(U2, au2, bu2);
    upk(V0, av0, bv0); upk(V1, av1, bv1); upk(V2, av2, bv2);
    upk(V3, av3, bv3); upk(V4, av4, bv4);

    float4* op = reinterpret_cast<float4*>(out + (size_t)i0 * 8);
    op[0] = make_float4(au0, au1, au2, av0);
    op[1] = make_float4(av1, av2, av3, av4);
    if (i0 + 1 < n) {
        op[2] = make_float4(bu0, bu1, bu2, bv0);
        op[3] = make_float4(bv1, bv2, bv3, bv4);
    }
}

extern "C" void kernel_launch(void* const* d_in, const int* in_sizes, int n_in,
                              void* d_out, int out_size)
{
    const float* x  = (const float*)d_in[0];
    const float* W0 = (const float*)d_in[1];
    const float* b0 = (const float*)d_in[2];
    const float* W1 = (const float*)d_in[3];
    const float* b1 = (const float*)d_in[4];
    const float* W2 = (const float*)d_in[5];
    const float* b2 = (const float*)d_in[6];
    float* out = (float*)d_out;

    int n = in_sizes[0];
    int npairs = (n + 1) / 2;
    int threads = 256;
    int blocks = (npairs + threads - 1) / threads;
    pinn_jet2_kernel<<<blocks, threads>>>(x, W0, b0, W1, b1, W2, b2, out, n);
}

// round 3
// speedup vs baseline: 1.3141x; 1.3141x over previous
#include <cuda_runtime.h>

// PINN 5-jet propagation, 1 point/thread, fast MUFU tanh.
// Per point: push (val, d1..d4 w.r.t x) through 1->8 tanh -> 8 tanh -> 2 linear.
// Outputs per point: [u, u_x, u_xx, w, w_x, w_xx, w_xxx, w_xxxx].

// tanh via exp: t = 1 - 2/(exp(2z)+1); s = 1 - t^2. ~1e-6 accurate, 6 instrs.
__device__ __forceinline__ float tanh_fast(float z, float& s) {
    float e, r;
    asm("ex2.approx.f32 %0, %1;" : "=f"(e) : "f"(z * 2.8853900817779268f)); // 2*log2(e)
    asm("rcp.approx.f32 %0, %1;" : "=f"(r) : "f"(e + 1.0f));
    float t = fmaf(-2.0f, r, 1.0f);
    s = fmaf(-t, t, 1.0f);
    return t;
}

__global__ __launch_bounds__(256)
void pinn_jet_kernel(const float* __restrict__ x,
                     const float* __restrict__ gW0, const float* __restrict__ gb0,
                     const float* __restrict__ gW1, const float* __restrict__ gb1,
                     const float* __restrict__ gW2, const float* __restrict__ gb2,
                     float* __restrict__ out, int n)
{
    __shared__ float sW0[8], sW0p2[8], sW0p3[8], sW0p4[8], sb0[8];
    __shared__ float sW1[64], sb1[8], sW2u[8], sW2v[8], sb2[2];
    {
        int t = threadIdx.x;
        if (t < 64) sW1[t] = gW1[t];
        if (t < 8) {
            float w = gW0[t], w2 = w * w;
            sW0[t] = w; sW0p2[t] = w2; sW0p3[t] = w2 * w; sW0p4[t] = w2 * w2;
            sb0[t] = gb0[t];
            sb1[t] = gb1[t];
            sW2u[t] = gW2[t];
            sW2v[t] = gW2[8 + t];
        }
        if (t < 2) sb2[t] = gb2[t];
    }
    __syncthreads();

    int i = blockIdx.x * blockDim.x + threadIdx.x;
    if (i >= n) return;

    const float xv = x[i];

    // ---- Layer 0: scalar input -> tanh jet (z1 = w, z2..z4 = 0) ----
    float h0[8], h1[8], h2[8], h3[8], h4[8];
#pragma unroll
    for (int j = 0; j < 8; ++j) {
        float z0 = fmaf(sW0[j], xv, sb0[j]);
        float s;
        float t  = tanh_fast(z0, s);
        float ts = t * s;
        float tt = t * t;
        float d2 = -2.0f * ts;                          // t''
        float d3 = s * fmaf(6.0f, tt, -2.0f);           // t'''
        float d4 = ts * fmaf(-24.0f, tt, 16.0f);        // t''''
        h0[j] = t;
        h1[j] = s  * sW0[j];
        h2[j] = d2 * sW0p2[j];
        h3[j] = d3 * sW0p3[j];
        h4[j] = d4 * sW0p4[j];
    }

    // ---- Layer 1 (8x8) + tanh jet, output layer fused in ----
    float u0 = sb2[0], u1 = 0.f, u2 = 0.f;
    float v0 = sb2[1], v1 = 0.f, v2 = 0.f, v3 = 0.f, v4 = 0.f;

#pragma unroll
    for (int j = 0; j < 8; ++j) {
        float z0 = sb1[j], z1 = 0.f, z2 = 0.f, z3 = 0.f, z4 = 0.f;
#pragma unroll
        for (int k = 0; k < 8; ++k) {
            float w = sW1[j * 8 + k];
            z0 = fmaf(w, h0[k], z0);
            z1 = fmaf(w, h1[k], z1);
            z2 = fmaf(w, h2[k], z2);
            z3 = fmaf(w, h3[k], z3);
            z4 = fmaf(w, h4[k], z4);
        }
        float s;
        float t  = tanh_fast(z0, s);
        float ts = t * s;
        float tt = t * t;
        float d2 = -2.0f * ts;
        float d3 = s * fmaf(6.0f, tt, -2.0f);
        float d4 = ts * fmaf(-24.0f, tt, 16.0f);

        float z1_2 = z1 * z1;
        // Faa di Bruno, orders 0..4
        float g0 = t;
        float g1 = s * z1;
        float g2 = fmaf(d2, z1_2, s * z2);
        float g3 = fmaf(d3 * z1_2, z1, fmaf(3.0f * d2, z1 * z2, s * z3));
        float g4 = fmaf(d4, z1_2 * z1_2,
                   fmaf(6.0f * d3, z1_2 * z2,
                   fmaf(d2, fmaf(3.0f * z2, z2, 4.0f * (z1 * z3)),
                        s * z4)));

        float wu = sW2u[j];
        float wv = sW2v[j];
        u0 = fmaf(wu, g0, u0);
        u1 = fmaf(wu, g1, u1);
        u2 = fmaf(wu, g2, u2);
        v0 = fmaf(wv, g0, v0);
        v1 = fmaf(wv, g1, v1);
        v2 = fmaf(wv, g2, v2);
        v3 = fmaf(wv, g3, v3);
        v4 = fmaf(wv, g4, v4);
    }

    // ---- Store [u, u_x, u_xx, w, w_x, w_xx, w_xxx, w_xxxx] ----
    float4* op = reinterpret_cast<float4*>(out + (size_t)i * 8);
    op[0] = make_float4(u0, u1, u2, v0);
    op[1] = make_float4(v1, v2, v3, v4);
}

extern "C" void kernel_launch(void* const* d_in, const int* in_sizes, int n_in,
                              void* d_out, int out_size)
{
    const float* x  = (const float*)d_in[0];
    const float* W0 = (const float*)d_in[1];
    const float* b0 = (const float*)d_in[2];
    const float* W1 = (const float*)d_in[3];
    const float* b1 = (const float*)d_in[4];
    const float* W2 = (const float*)d_in[5];
    const float* b2 = (const float*)d_in[6];
    float* out = (float*)d_out;

    int n = in_sizes[0];
    int threads = 256;
    int blocks = (n + threads - 1) / threads;
    pinn_jet_kernel<<<blocks, threads>>>(x, W0, b0, W1, b1, W2, b2, out, n);
}